// round 1
// baseline (speedup 1.0000x reference)
#include <cuda_runtime.h>
#include <cuda_fp16.h>
#include <cstdint>

#define NN   50000
#define EE   800000
#define DD   128
#define RR   8
#define NSEG (NN*RR)        // 400000 segments (node, relation)
#define AW   1152           // A-matrix row width: 1024 (mean, [B=2][R=8][64]) + 128 (feat fp16)
#define KW   640            // GEMM K per output block: 512 (mean) + 128 (root)
#define NB_SCAN ((NSEG + 1023) / 1024)   // 391

// ---------------- device scratch (static; no allocations allowed) ----------------
__device__ int    g_cnt[NSEG];
__device__ int    g_ptr[NSEG];
__device__ int    g_pos[NSEG];
__device__ int    g_bsum[512];
__device__ int    g_srcs[EE];
__device__ __half g_A[(size_t)NN * AW];     // fp16 A-matrix (rebuilt per layer)
__device__ float  g_h[(size_t)NN * DD];     // layer-1 output (fp32)
__device__ __half g_W[2 * 2 * KW * 64];     // [layer][block][k][64] fp16 fused weights

// ---------------- weight prep: fuse W (block-diag) + root into Wcat ----------------
__global__ void k_prep_w(const float* __restrict__ W1, const float* __restrict__ root1,
                         const float* __restrict__ W2, const float* __restrict__ root2) {
    int i = blockIdx.x * blockDim.x + threadIdx.x;
    const int total = 2 * 2 * KW * 64;
    if (i >= total) return;
    int j = i;
    int l = j / (2 * KW * 64); j -= l * (2 * KW * 64);
    int b = j / (KW * 64);     j -= b * (KW * 64);
    int k = j / 64;
    int d = j - k * 64;
    const float* W    = l ? W2    : W1;
    const float* root = l ? root2 : root1;
    float v;
    if (k < 512) {                       // relation blocks: k = r*64 + c
        int r = k >> 6, c = k & 63;
        v = W[((r * 2 + b) * 64 + c) * 64 + d];
    } else {                             // root rows
        int din = k - 512;
        v = root[din * 128 + b * 64 + d];
    }
    g_W[i] = __float2half(v);
}

// ---------------- CSR build ----------------
__global__ void k_zero_cnt() {
    int i = blockIdx.x * blockDim.x + threadIdx.x;
    if (i < NSEG) g_cnt[i] = 0;
}

__global__ void k_hist(const int* __restrict__ dst, const int* __restrict__ et) {
    int i = blockIdx.x * blockDim.x + threadIdx.x;
    if (i < EE) atomicAdd(&g_cnt[dst[i] * RR + et[i]], 1);
}

__global__ void k_scan1() {   // grid NB_SCAN, block 1024: per-block exclusive scan + block totals
    int i = blockIdx.x * 1024 + threadIdx.x;
    int v = (i < NSEG) ? g_cnt[i] : 0;
    int lane = threadIdx.x & 31, warp = threadIdx.x >> 5;
    int x = v;
    #pragma unroll
    for (int d = 1; d < 32; d <<= 1) {
        int y = __shfl_up_sync(0xffffffffu, x, d);
        if (lane >= d) x += y;
    }
    __shared__ int ws[32];
    if (lane == 31) ws[warp] = x;
    __syncthreads();
    if (warp == 0) {
        int s = ws[lane];
        #pragma unroll
        for (int d = 1; d < 32; d <<= 1) {
            int y = __shfl_up_sync(0xffffffffu, s, d);
            if (lane >= d) s += y;
        }
        ws[lane] = s;
    }
    __syncthreads();
    int off = warp ? ws[warp - 1] : 0;
    int inc = x + off;
    if (i < NSEG) g_ptr[i] = inc - v;
    if (threadIdx.x == 1023) g_bsum[blockIdx.x] = inc;
}

__global__ void k_scan2() {   // 1 block, 512 threads: exclusive scan of block totals
    int i = threadIdx.x;
    int v = (i < NB_SCAN) ? g_bsum[i] : 0;
    int lane = i & 31, warp = i >> 5;
    int x = v;
    #pragma unroll
    for (int d = 1; d < 32; d <<= 1) {
        int y = __shfl_up_sync(0xffffffffu, x, d);
        if (lane >= d) x += y;
    }
    __shared__ int ws[16];
    if (lane == 31) ws[warp] = x;
    __syncthreads();
    if (warp == 0 && lane < 16) {
        int s = ws[lane];
        #pragma unroll
        for (int d = 1; d < 16; d <<= 1) {
            int y = __shfl_up_sync(0x0000ffffu, s, d);
            if (lane >= d) s += y;
        }
        ws[lane] = s;
    }
    __syncthreads();
    int off = warp ? ws[warp - 1] : 0;
    int ex = x + off - v;
    __syncthreads();
    if (i < NB_SCAN) g_bsum[i] = ex;
}

__global__ void k_scan3() {
    int i = blockIdx.x * blockDim.x + threadIdx.x;
    if (i < NSEG) {
        int p = g_ptr[i] + g_bsum[i >> 10];
        g_ptr[i] = p;
        g_pos[i] = p;
    }
}

__global__ void k_scatter(const int* __restrict__ src, const int* __restrict__ dst,
                          const int* __restrict__ et) {
    int i = blockIdx.x * blockDim.x + threadIdx.x;
    if (i < EE) {
        int seg = dst[i] * RR + et[i];
        int p = atomicAdd(&g_pos[seg], 1);
        g_srcs[p] = src[i];
    }
}

// ---------------- aggregation: warp per (node,relation) segment -> fp16 A cols ----------------
__global__ void k_agg(const float* __restrict__ x, int layer) {
    const float* feat = layer ? (const float*)g_h : x;
    int w = (blockIdx.x * blockDim.x + threadIdx.x) >> 5;
    int lane = threadIdx.x & 31;
    if (w >= NSEG) return;
    int n = w >> 3, r = w & 7;
    int c = g_cnt[w], base = g_ptr[w];
    float4 acc = make_float4(0.f, 0.f, 0.f, 0.f);
    const float4* f4 = (const float4*)feat;
    for (int e = 0; e < c; ++e) {
        int s = g_srcs[base + e];
        float4 v = __ldg(&f4[(size_t)s * 32 + lane]);
        acc.x += v.x; acc.y += v.y; acc.z += v.z; acc.w += v.w;
    }
    float sc = 1.0f / (float)max(c, 1);
    int d0 = lane * 4;
    int col = (d0 < 64) ? (r * 64 + d0) : (512 + r * 64 + (d0 - 64));
    __half2* o = reinterpret_cast<__half2*>(&g_A[(size_t)n * AW + col]);
    o[0] = __floats2half2_rn(acc.x * sc, acc.y * sc);
    o[1] = __floats2half2_rn(acc.z * sc, acc.w * sc);
}

// ---------------- fp16 copy of features into A cols [1024,1152) ----------------
__global__ void k_copyx(const float* __restrict__ x, int layer) {
    const float* feat = layer ? (const float*)g_h : x;
    int i = blockIdx.x * blockDim.x + threadIdx.x;
    if (i >= NN * 32) return;
    int n = i >> 5, lane = i & 31;
    float4 v = ((const float4*)feat)[i];
    __half2* o = reinterpret_cast<__half2*>(&g_A[(size_t)n * AW + 1024 + lane * 4]);
    o[0] = __floats2half2_rn(v.x, v.y);
    o[1] = __floats2half2_rn(v.z, v.w);
}

// ---------------- GEMM: Out[:, 64b:64b+64] = A_b (Nx640) @ Wcat_b (640x64), fp16 mma ----------------
__global__ void __launch_bounds__(256, 1) k_gemm(int layer, const float* __restrict__ bias,
                                                 float* __restrict__ dout) {
    __shared__ __half As[128][72];
    __shared__ __half Bs[64][72];
    const __half* B = g_W + ((size_t)layer * 2 + blockIdx.y) * KW * 64;
    float* out = (layer == 0) ? (float*)g_h : dout;
    int relu = (layer == 0);
    int b = blockIdx.y;
    int row0 = blockIdx.x * 128;
    int tid = threadIdx.x, warp = tid >> 5, lane = tid & 31;

    float acc[8][4];
    #pragma unroll
    for (int i = 0; i < 8; ++i)
        #pragma unroll
        for (int j = 0; j < 4; ++j) acc[i][j] = 0.f;

    for (int k0 = 0; k0 < KW; k0 += 64) {
        int cb = (k0 < 512) ? (b * 512 + k0) : (512 + k0);
        // stage A: 128 rows x 64 cols fp16
        #pragma unroll
        for (int i = tid; i < 1024; i += 256) {
            int r = i >> 3, c8 = (i & 7) * 8;
            int grow = row0 + r;
            int4 v = make_int4(0, 0, 0, 0);
            if (grow < NN) v = *(const int4*)(g_A + (size_t)grow * AW + cb + c8);
            *(int4*)(&As[r][c8]) = v;
        }
        // stage B: 64 rows x 64 cols fp16
        #pragma unroll
        for (int i = tid; i < 512; i += 256) {
            int r = i >> 3, c8 = (i & 7) * 8;
            *(int4*)(&Bs[r][c8]) = *(const int4*)(B + (size_t)(k0 + r) * 64 + c8);
        }
        __syncthreads();

        #pragma unroll
        for (int ks = 0; ks < 64; ks += 16) {
            uint32_t a0, a1, a2, a3;
            {
                uint32_t addr = (uint32_t)__cvta_generic_to_shared(
                    &As[warp * 16 + (lane & 15)][ks + (lane >> 4) * 8]);
                asm volatile("ldmatrix.sync.aligned.m8n8.x4.shared.b16 {%0,%1,%2,%3},[%4];"
                             : "=r"(a0), "=r"(a1), "=r"(a2), "=r"(a3) : "r"(addr));
            }
            #pragma unroll
            for (int np = 0; np < 4; ++np) {
                uint32_t b0, b1, b2, b3;
                uint32_t addr = (uint32_t)__cvta_generic_to_shared(
                    &Bs[ks + (lane & 15)][np * 16 + (lane >> 4) * 8]);
                asm volatile("ldmatrix.sync.aligned.m8n8.x4.trans.shared.b16 {%0,%1,%2,%3},[%4];"
                             : "=r"(b0), "=r"(b1), "=r"(b2), "=r"(b3) : "r"(addr));
                asm volatile("mma.sync.aligned.m16n8k16.row.col.f32.f16.f16.f32 "
                             "{%0,%1,%2,%3},{%4,%5,%6,%7},{%8,%9},{%0,%1,%2,%3};"
                             : "+f"(acc[np*2][0]), "+f"(acc[np*2][1]),
                               "+f"(acc[np*2][2]), "+f"(acc[np*2][3])
                             : "r"(a0), "r"(a1), "r"(a2), "r"(a3), "r"(b0), "r"(b1));
                asm volatile("mma.sync.aligned.m16n8k16.row.col.f32.f16.f16.f32 "
                             "{%0,%1,%2,%3},{%4,%5,%6,%7},{%8,%9},{%0,%1,%2,%3};"
                             : "+f"(acc[np*2+1][0]), "+f"(acc[np*2+1][1]),
                               "+f"(acc[np*2+1][2]), "+f"(acc[np*2+1][3])
                             : "r"(a0), "r"(a1), "r"(a2), "r"(a3), "r"(b2), "r"(b3));
            }
        }
        __syncthreads();
    }

    // epilogue: + bias, optional ReLU, write fp32
    int rbase = row0 + warp * 16 + (lane >> 2);
    #pragma unroll
    for (int nt = 0; nt < 8; ++nt) {
        int col = b * 64 + nt * 8 + (lane & 3) * 2;
        float bv0 = bias[col], bv1 = bias[col + 1];
        #pragma unroll
        for (int h = 0; h < 2; ++h) {
            int row = rbase + h * 8;
            if (row < NN) {
                float v0 = acc[nt][h * 2 + 0] + bv0;
                float v1 = acc[nt][h * 2 + 1] + bv1;
                if (relu) { v0 = fmaxf(v0, 0.f); v1 = fmaxf(v1, 0.f); }
                out[(size_t)row * 128 + col]     = v0;
                out[(size_t)row * 128 + col + 1] = v1;
            }
        }
    }
}

// ---------------- launcher ----------------
extern "C" void kernel_launch(void* const* d_in, const int* in_sizes, int n_in,
                              void* d_out, int out_size) {
    const float* x    = (const float*)d_in[0];
    const int*   ei   = (const int*)  d_in[1];
    const int*   et   = (const int*)  d_in[2];
    const float* W1   = (const float*)d_in[3];
    const float* root1= (const float*)d_in[4];
    const float* b1   = (const float*)d_in[5];
    const float* W2   = (const float*)d_in[6];
    const float* root2= (const float*)d_in[7];
    const float* b2   = (const float*)d_in[8];
    float* out = (float*)d_out;
    const int* src = ei;
    const int* dst = ei + EE;

    k_prep_w<<<(2 * 2 * KW * 64 + 255) / 256, 256>>>(W1, root1, W2, root2);

    // CSR build (shared by both layers)
    k_zero_cnt<<<(NSEG + 255) / 256, 256>>>();
    k_hist<<<(EE + 255) / 256, 256>>>(dst, et);
    k_scan1<<<NB_SCAN, 1024>>>();
    k_scan2<<<1, 512>>>();
    k_scan3<<<(NSEG + 255) / 256, 256>>>();
    k_scatter<<<(EE + 255) / 256, 256>>>(src, dst, et);

    // layer 1
    k_agg<<<NSEG / 8, 256>>>(x, 0);
    k_copyx<<<(NN * 32 + 255) / 256, 256>>>(x, 0);
    k_gemm<<<dim3((NN + 127) / 128, 2), 256>>>(0, b1, out);

    // layer 2
    k_agg<<<NSEG / 8, 256>>>(x, 1);
    k_copyx<<<(NN * 32 + 255) / 256, 256>>>(x, 1);
    k_gemm<<<dim3((NN + 127) / 128, 2), 256>>>(1, b2, out);
}

// round 2
// speedup vs baseline: 1.0550x; 1.0550x over previous
#include <cuda_runtime.h>
#include <cuda_fp16.h>
#include <cstdint>

#define NN   50000
#define EE   800000
#define DD   128
#define RR   8
#define NSEG (NN*RR)        // 400000 segments (node, relation)
#define AW   1152           // A row width: 1024 (mean, [B=2][R=8][64]) + 128 (feat fp16)
#define KW   640            // GEMM K per output block: 512 (mean) + 128 (root)
#define NB_SCAN ((NSEG + 1023) / 1024)   // 391
#define WTOT (2 * 2 * KW * 64)

// ---------------- device scratch ----------------
__device__ int    g_cnt[NSEG];
__device__ int    g_ptr[NSEG];
__device__ int    g_pos[NSEG];
__device__ int    g_bsum[512];
__device__ int    g_srcs[EE];
__device__ __half g_A[(size_t)NN * AW];       // fp16 A-matrix (rebuilt per layer)
__device__ __half g_feat[2][(size_t)NN * DD]; // fp16 features: [0]=x, [1]=h
__device__ __half g_W[WTOT];                  // [layer][block][k][64] fused weights

// ---------------- cp.async helpers ----------------
__device__ __forceinline__ void cp_async16(uint32_t dst, const void* src, int src_bytes) {
    asm volatile("cp.async.cg.shared.global [%0], [%1], 16, %2;"
                 :: "r"(dst), "l"(src), "r"(src_bytes));
}
__device__ __forceinline__ void cp_commit() { asm volatile("cp.async.commit_group;"); }
template <int N>
__device__ __forceinline__ void cp_wait() { asm volatile("cp.async.wait_group %0;" :: "n"(N)); }

// ---------------- weight prep + counter zero (fused) ----------------
__global__ void k_prep(const float* __restrict__ W1, const float* __restrict__ root1,
                       const float* __restrict__ W2, const float* __restrict__ root2) {
    int i = blockIdx.x * blockDim.x + threadIdx.x;
    if (i < NSEG) g_cnt[i] = 0;
    if (i >= WTOT) return;
    int j = i;
    int l = j / (2 * KW * 64); j -= l * (2 * KW * 64);
    int b = j / (KW * 64);     j -= b * (KW * 64);
    int k = j / 64;
    int d = j - k * 64;
    const float* W    = l ? W2    : W1;
    const float* root = l ? root2 : root1;
    float v;
    if (k < 512) {                       // relation blocks: k = r*64 + c
        int r = k >> 6, c = k & 63;
        v = W[((r * 2 + b) * 64 + c) * 64 + d];
    } else {                             // root rows
        int din = k - 512;
        v = root[din * 128 + b * 64 + d];
    }
    g_W[i] = __float2half(v);
}

// ---------------- CSR build ----------------
__global__ void k_hist(const int* __restrict__ dst, const int* __restrict__ et) {
    int i = blockIdx.x * blockDim.x + threadIdx.x;
    if (i < EE) atomicAdd(&g_cnt[dst[i] * RR + et[i]], 1);
}

__global__ void k_scan1() {
    int i = blockIdx.x * 1024 + threadIdx.x;
    int v = (i < NSEG) ? g_cnt[i] : 0;
    int lane = threadIdx.x & 31, warp = threadIdx.x >> 5;
    int x = v;
    #pragma unroll
    for (int d = 1; d < 32; d <<= 1) {
        int y = __shfl_up_sync(0xffffffffu, x, d);
        if (lane >= d) x += y;
    }
    __shared__ int ws[32];
    if (lane == 31) ws[warp] = x;
    __syncthreads();
    if (warp == 0) {
        int s = ws[lane];
        #pragma unroll
        for (int d = 1; d < 32; d <<= 1) {
            int y = __shfl_up_sync(0xffffffffu, s, d);
            if (lane >= d) s += y;
        }
        ws[lane] = s;
    }
    __syncthreads();
    int off = warp ? ws[warp - 1] : 0;
    int inc = x + off;
    if (i < NSEG) g_ptr[i] = inc - v;
    if (threadIdx.x == 1023) g_bsum[blockIdx.x] = inc;
}

__global__ void k_scan2() {
    int i = threadIdx.x;
    int v = (i < NB_SCAN) ? g_bsum[i] : 0;
    int lane = i & 31, warp = i >> 5;
    int x = v;
    #pragma unroll
    for (int d = 1; d < 32; d <<= 1) {
        int y = __shfl_up_sync(0xffffffffu, x, d);
        if (lane >= d) x += y;
    }
    __shared__ int ws[16];
    if (lane == 31) ws[warp] = x;
    __syncthreads();
    if (warp == 0 && lane < 16) {
        int s = ws[lane];
        #pragma unroll
        for (int d = 1; d < 16; d <<= 1) {
            int y = __shfl_up_sync(0x0000ffffu, s, d);
            if (lane >= d) s += y;
        }
        ws[lane] = s;
    }
    __syncthreads();
    int off = warp ? ws[warp - 1] : 0;
    int ex = x + off - v;
    __syncthreads();
    if (i < NB_SCAN) g_bsum[i] = ex;
}

__global__ void k_scan3() {
    int i = blockIdx.x * blockDim.x + threadIdx.x;
    if (i < NSEG) {
        int p = g_ptr[i] + g_bsum[i >> 10];
        g_ptr[i] = p;
        g_pos[i] = p;
    }
}

__global__ void k_scatter(const int* __restrict__ src, const int* __restrict__ dst,
                          const int* __restrict__ et) {
    int i = blockIdx.x * blockDim.x + threadIdx.x;
    if (i < EE) {
        int seg = dst[i] * RR + et[i];
        int p = atomicAdd(&g_pos[seg], 1);
        g_srcs[p] = src[i];
    }
}

// ---------------- fp16 conversion of x: -> g_feat[0] and A cols [1024,1152) ----------------
__global__ void k_copyx(const float* __restrict__ x) {
    int i = blockIdx.x * blockDim.x + threadIdx.x;
    if (i >= NN * 32) return;
    int n = i >> 5, lane = i & 31;
    float4 v = ((const float4*)x)[i];
    __half2 h0 = __floats2half2_rn(v.x, v.y);
    __half2 h1 = __floats2half2_rn(v.z, v.w);
    __half2* f = reinterpret_cast<__half2*>(&g_feat[0][(size_t)n * DD + lane * 4]);
    f[0] = h0; f[1] = h1;
    __half2* o = reinterpret_cast<__half2*>(&g_A[(size_t)n * AW + 1024 + lane * 4]);
    o[0] = h0; o[1] = h1;
}

// ---------------- copy h (fp16) into A cols [1024,1152) ----------------
__global__ void k_copyh() {
    int i = blockIdx.x * blockDim.x + threadIdx.x;
    if (i >= NN * 16) return;
    int n = i >> 4, c8 = (i & 15) * 8;
    int4 v = *(const int4*)(&g_feat[1][(size_t)n * DD + c8]);
    *(int4*)(&g_A[(size_t)n * AW + 1024 + c8]) = v;
}

// ---------------- aggregation: warp per (node,relation) segment, fp16 gather ----------------
__global__ void k_agg(int layer) {
    const __half* feat = g_feat[layer];
    int w = (blockIdx.x * blockDim.x + threadIdx.x) >> 5;
    int lane = threadIdx.x & 31;
    if (w >= NSEG) return;
    int n = w >> 3, r = w & 7;
    int c = g_cnt[w], base = g_ptr[w];
    float acc0 = 0.f, acc1 = 0.f, acc2 = 0.f, acc3 = 0.f;
    for (int e0 = 0; e0 < c; e0 += 32) {
        int nIdx = min(32, c - e0);
        int sIdx = (lane < nIdx) ? g_srcs[base + e0 + lane] : 0;
        for (int e = 0; e < nIdx; ++e) {
            int s = __shfl_sync(0xffffffffu, sIdx, e);
            uint2 v = *(const uint2*)(feat + (size_t)s * DD + lane * 4);
            __half2 h0 = *reinterpret_cast<__half2*>(&v.x);
            __half2 h1 = *reinterpret_cast<__half2*>(&v.y);
            float2 f0 = __half22float2(h0);
            float2 f1 = __half22float2(h1);
            acc0 += f0.x; acc1 += f0.y; acc2 += f1.x; acc3 += f1.y;
        }
    }
    float sc = 1.0f / (float)max(c, 1);
    int d0 = lane * 4;
    int col = (d0 < 64) ? (r * 64 + d0) : (512 + r * 64 + (d0 - 64));
    __half2* o = reinterpret_cast<__half2*>(&g_A[(size_t)n * AW + col]);
    o[0] = __floats2half2_rn(acc0 * sc, acc1 * sc);
    o[1] = __floats2half2_rn(acc2 * sc, acc3 * sc);
}

// ---------------- GEMM: Out[:, 64b:64b+64] = A_b (Nx640) @ Wcat_b (640x64) ----------------
__global__ void __launch_bounds__(256) k_gemm(int layer, const float* __restrict__ bias,
                                              float* __restrict__ dout) {
    __shared__ __half As[2][128][72];
    __shared__ __half Bs[2][64][72];
    const __half* B = g_W + ((size_t)layer * 2 + blockIdx.y) * KW * 64;
    int b = blockIdx.y;
    int row0 = blockIdx.x * 128;
    int tid = threadIdx.x, warp = tid >> 5, lane = tid & 31;

    float acc[8][4];
    #pragma unroll
    for (int i = 0; i < 8; ++i)
        #pragma unroll
        for (int j = 0; j < 4; ++j) acc[i][j] = 0.f;

    // stage loader: kt in [0,10)
    auto load_stage = [&](int st, int kt) {
        int k0 = kt * 64;
        int cb = (k0 < 512) ? (b * 512 + k0) : (512 + k0);
        #pragma unroll
        for (int i = tid; i < 1024; i += 256) {   // A: 128 x 64 halfs = 1024 x 16B
            int r = i >> 3, c8 = (i & 7) * 8;
            int grow = row0 + r;
            int ok = (grow < NN);
            const void* src = g_A + (size_t)(ok ? grow : 0) * AW + cb + c8;
            uint32_t dst = (uint32_t)__cvta_generic_to_shared(&As[st][r][c8]);
            cp_async16(dst, src, ok ? 16 : 0);
        }
        #pragma unroll
        for (int i = tid; i < 512; i += 256) {    // B: 64 x 64 halfs = 512 x 16B
            int r = i >> 3, c8 = (i & 7) * 8;
            uint32_t dst = (uint32_t)__cvta_generic_to_shared(&Bs[st][r][c8]);
            cp_async16(dst, B + (size_t)(k0 + r) * 64 + c8, 16);
        }
        cp_commit();
    };

    load_stage(0, 0);

    for (int kt = 0; kt < 10; ++kt) {
        int st = kt & 1;
        if (kt < 9) {
            load_stage(st ^ 1, kt + 1);
            cp_wait<1>();
        } else {
            cp_wait<0>();
        }
        __syncthreads();

        #pragma unroll
        for (int ks = 0; ks < 64; ks += 16) {
            uint32_t a0, a1, a2, a3;
            {
                uint32_t addr = (uint32_t)__cvta_generic_to_shared(
                    &As[st][warp * 16 + (lane & 15)][ks + (lane >> 4) * 8]);
                asm volatile("ldmatrix.sync.aligned.m8n8.x4.shared.b16 {%0,%1,%2,%3},[%4];"
                             : "=r"(a0), "=r"(a1), "=r"(a2), "=r"(a3) : "r"(addr));
            }
            #pragma unroll
            for (int np = 0; np < 4; ++np) {
                uint32_t b0, b1, b2, b3;
                uint32_t addr = (uint32_t)__cvta_generic_to_shared(
                    &Bs[st][ks + (lane & 15)][np * 16 + (lane >> 4) * 8]);
                asm volatile("ldmatrix.sync.aligned.m8n8.x4.trans.shared.b16 {%0,%1,%2,%3},[%4];"
                             : "=r"(b0), "=r"(b1), "=r"(b2), "=r"(b3) : "r"(addr));
                asm volatile("mma.sync.aligned.m16n8k16.row.col.f32.f16.f16.f32 "
                             "{%0,%1,%2,%3},{%4,%5,%6,%7},{%8,%9},{%0,%1,%2,%3};"
                             : "+f"(acc[np*2][0]), "+f"(acc[np*2][1]),
                               "+f"(acc[np*2][2]), "+f"(acc[np*2][3])
                             : "r"(a0), "r"(a1), "r"(a2), "r"(a3), "r"(b0), "r"(b1));
                asm volatile("mma.sync.aligned.m16n8k16.row.col.f32.f16.f16.f32 "
                             "{%0,%1,%2,%3},{%4,%5,%6,%7},{%8,%9},{%0,%1,%2,%3};"
                             : "+f"(acc[np*2+1][0]), "+f"(acc[np*2+1][1]),
                               "+f"(acc[np*2+1][2]), "+f"(acc[np*2+1][3])
                             : "r"(a0), "r"(a1), "r"(a2), "r"(a3), "r"(b2), "r"(b3));
            }
        }
        __syncthreads();
    }

    // epilogue: + bias; layer 0 -> ReLU + fp16 h; layer 1 -> fp32 d_out
    int rbase = row0 + warp * 16 + (lane >> 2);
    #pragma unroll
    for (int nt = 0; nt < 8; ++nt) {
        int col = b * 64 + nt * 8 + (lane & 3) * 2;
        float bv0 = bias[col], bv1 = bias[col + 1];
        #pragma unroll
        for (int h = 0; h < 2; ++h) {
            int row = rbase + h * 8;
            if (row < NN) {
                float v0 = acc[nt][h * 2 + 0] + bv0;
                float v1 = acc[nt][h * 2 + 1] + bv1;
                if (layer == 0) {
                    v0 = fmaxf(v0, 0.f); v1 = fmaxf(v1, 0.f);
                    *reinterpret_cast<__half2*>(&g_feat[1][(size_t)row * DD + col]) =
                        __floats2half2_rn(v0, v1);
                } else {
                    dout[(size_t)row * DD + col]     = v0;
                    dout[(size_t)row * DD + col + 1] = v1;
                }
            }
        }
    }
}

// ---------------- launcher ----------------
extern "C" void kernel_launch(void* const* d_in, const int* in_sizes, int n_in,
                              void* d_out, int out_size) {
    const float* x    = (const float*)d_in[0];
    const int*   ei   = (const int*)  d_in[1];
    const int*   et   = (const int*)  d_in[2];
    const float* W1   = (const float*)d_in[3];
    const float* root1= (const float*)d_in[4];
    const float* b1   = (const float*)d_in[5];
    const float* W2   = (const float*)d_in[6];
    const float* root2= (const float*)d_in[7];
    const float* b2   = (const float*)d_in[8];
    float* out = (float*)d_out;
    const int* src = ei;
    const int* dst = ei + EE;

    k_prep<<<(NSEG + 255) / 256, 256>>>(W1, root1, W2, root2);

    // CSR build (shared by both layers)
    k_hist<<<(EE + 255) / 256, 256>>>(dst, et);
    k_scan1<<<NB_SCAN, 1024>>>();
    k_scan2<<<1, 512>>>();
    k_scan3<<<(NSEG + 255) / 256, 256>>>();
    k_scatter<<<(EE + 255) / 256, 256>>>(src, dst, et);

    // layer 1
    k_copyx<<<(NN * 32 + 255) / 256, 256>>>(x);
    k_agg<<<NSEG / 8, 256>>>(0);
    k_gemm<<<dim3((NN + 127) / 128, 2), 256>>>(0, b1, out);

    // layer 2
    k_copyh<<<(NN * 16 + 255) / 256, 256>>>();
    k_agg<<<NSEG / 8, 256>>>(1);
    k_gemm<<<dim3((NN + 127) / 128, 2), 256>>>(1, b2, out);
}